// round 6
// baseline (speedup 1.0000x reference)
#include <cuda_runtime.h>
#include <math.h>

#define BB 2
#define LL 1024
#define DD 1024
#define NN 16
#define RR 64

// scratch (no device allocations allowed)
__device__ float g_tmp[BB * LL * RR];
__device__ float g_delta[BB * LL * DD];
__device__ float g_Bt[BB * LL * NN];
__device__ float g_Ct[BB * LL * NN];

// ---------------- fused projection: tmp, Bt, Ct in one pass over x ----------
// TM=8 rows/block, 256 blocks (2 blocks/SM) for latency hiding. Every output
// keeps the exact full-length k-ascending fmaf chain => bit-identical.
__global__ void __launch_bounds__(256) proj_fused(
    const float* __restrict__ A,   // x: [2048, 1024]
    const float* __restrict__ W1,  // W_dt1: [1024, 64]
    const float* __restrict__ WB,  // [1024, 16]
    const float* __restrict__ WC,  // [1024, 16]
    float* __restrict__ Tmp, float* __restrict__ Bt, float* __restrict__ Ct)
{
    __shared__ float As[8][64];
    __shared__ float W1s[64][64];
    __shared__ float WBs[64][16];
    __shared__ float WCs[64][16];

    int tid = threadIdx.x;
    int m0 = blockIdx.x * 8;

    // tmp role: thread -> rows (r0, r0+4), col nT
    int r0 = tid >> 6;        // 0..3
    int nT = tid & 63;        // 0..63
    // btct role (first 128 threads): row rB, col nB
    int rB = tid >> 4;        // 0..15 (valid < 8)
    int nB = tid & 15;        // 0..15
    bool doB = (rB < 8);

    float accT0 = 0.f, accT1 = 0.f;
    float accB = 0.f, accC = 0.f;

    for (int k0 = 0; k0 < 1024; k0 += 64) {
        __syncthreads();
        for (int i = tid; i < 8 * 64; i += 256) {
            int rr = i >> 6, kk = i & 63;
            As[rr][kk] = A[(size_t)(m0 + rr) * 1024 + (k0 + kk)];
        }
        for (int i = tid; i < 64 * 64; i += 256) {
            int kk = i >> 6, nn = i & 63;
            W1s[kk][nn] = W1[(size_t)(k0 + kk) * 64 + nn];
        }
        for (int i = tid; i < 64 * 16; i += 256) {
            int kk = i >> 4, nn = i & 15;
            WBs[kk][nn] = WB[(size_t)(k0 + kk) * 16 + nn];
            WCs[kk][nn] = WC[(size_t)(k0 + kk) * 16 + nn];
        }
        __syncthreads();

#pragma unroll
        for (int k = 0; k < 64; ++k) {
            float w = W1s[k][nT];
            accT0 = fmaf(As[r0][k],     w, accT0);
            accT1 = fmaf(As[r0 + 4][k], w, accT1);
            if (doB) {
                float a = As[rB][k];
                accB = fmaf(a, WBs[k][nB], accB);
                accC = fmaf(a, WCs[k][nB], accC);
            }
        }
    }

    Tmp[(size_t)(m0 + r0) * 64 + nT]     = accT0;
    Tmp[(size_t)(m0 + r0 + 4) * 64 + nT] = accT1;
    if (doB) {
        Bt[(size_t)(m0 + rB) * 16 + nB] = accB;
        Ct[(size_t)(m0 + rB) * 16 + nB] = accC;
    }
}

// ---------------- delta GEMM + softplus (unchanged numerics) ----------------
__global__ void __launch_bounds__(256) delta_gemm(
    const float* __restrict__ T, const float* __restrict__ W,
    float* __restrict__ C)
{
    __shared__ float ts[8][64];
    int tid = threadIdx.x;
    int m0 = blockIdx.y * 8;
    int n  = blockIdx.x * 256 + tid;

    for (int i = tid; i < 8 * 64; i += 256)
        ts[i / 64][i % 64] = T[(size_t)(m0 + i / 64) * 64 + (i % 64)];
    __syncthreads();

    float acc[8];
#pragma unroll
    for (int r = 0; r < 8; ++r) acc[r] = 0.f;

#pragma unroll
    for (int k = 0; k < 64; ++k) {
        float w = W[(size_t)k * 1024 + n];
#pragma unroll
        for (int r = 0; r < 8; ++r)
            acc[r] = fmaf(ts[r][k], w, acc[r]);
    }

#pragma unroll
    for (int r = 0; r < 8; ++r) {
        float v = acc[r];
        v = fmaxf(v, 0.f) + log1pf(expf(-fabsf(v)));
        C[(size_t)(m0 + r) * 1024 + n] = v;
    }
}

// ---------------- sequential resonance scan (op-for-op faithful) ----------------
// 1024 single-warp blocks: spreads 1024 warps over all 148 SMs (worst SM gets
// 7 instead of 8). The injection phase pa (h-independent) is explicitly
// computed one step ahead, right after the prefetch loads, so its atan2 sits
// in the shadow of the h-dependent chain. Per-chain op sequence unchanged.
__global__ void __launch_bounds__(32) scan_k(
    const float* __restrict__ x, const float* __restrict__ A_log,
    const float* __restrict__ Dskip, float* __restrict__ y)
{
    int tid = threadIdx.x;                // 0..31
    int g = (blockIdx.x << 1) | (tid >> 4);  // group id 0..2047
    int b = g >> 10;                      // 0..1
    int d = g & 1023;
    int n = tid & 15;

    float An = expf(A_log[n]);
    float phi = (float)n * 0.39269908169872414f;
    float sphi, cphi;
    sincosf(phi, &sphi, &cphi);
    float hx = __fmul_rn(0.01f, cphi), hy = __fmul_rn(0.01f, sphi);
    float dsk = Dskip[d];

    size_t rowbase = ((size_t)b * LL) * DD + d;
    const float* xp = x + rowbase;
    const float* dp = g_delta + rowbase;
    const float* bp = g_Bt + ((size_t)b * LL) * NN + n;
    const float* cp = g_Ct + ((size_t)b * LL) * NN + n;
    float* yp = y + rowbase;

    float xv = __ldg(xp);
    float dv = __ldg(dp);
    float bn = __ldg(bp);
    float cn = __ldg(cp);

    // h-independent step-t values, computed ahead of the dependent chain
    float u   = __fmul_rn(xv, bn);
    float ijx = __fmul_rn(u, cphi);
    float ijy = __fmul_rn(u, sphi);
    float pa  = atan2f(ijy, __fadd_rn(ijx, 1e-10f));
    float e   = __fadd_rn(1.0f, __fmul_rn(dv, An));

#pragma unroll 2
    for (int t = 0; t < LL; ++t) {
        int tn = (t < LL - 1) ? (t + 1) : t;
        float xv2 = __ldg(xp + (size_t)tn * DD);
        float dv2 = __ldg(dp + (size_t)tn * DD);
        float bn2 = __ldg(bp + tn * NN);
        float cn2 = __ldg(cp + tn * NN);

        // next-step h-independent values (fills this step's stall shadow)
        float u2   = __fmul_rn(xv2, bn2);
        float ijx2 = __fmul_rn(u2, cphi);
        float ijy2 = __fmul_rn(u2, sphi);
        float pa2  = atan2f(ijy2, __fadd_rn(ijx2, 1e-10f));
        float e2   = __fadd_rn(1.0f, __fmul_rn(dv2, An));

        // ---- fractal_compress(h, e) ----
        float mag = __fsqrt_rn(__fadd_rn(__fadd_rn(__fmul_rn(hx, hx), __fmul_rn(hy, hy)), 1e-8f));
        float ph  = atan2f(hy, __fadd_rn(hx, 1e-10f));
        float cm  = fminf(expf(__fmul_rn(e, logf(__fadd_rn(mag, 1e-8f)))), 10.0f);
        float sph, cph;
        sincosf(ph, &sph, &cph);
        float hcx = __fmul_rn(cm, cph);
        float hcy = __fmul_rn(cm, sph);

        // ---- resonance gate: gamma = 0.5 * cos((pa-pb)/2)^2 ----
        float pb = atan2f(hcy, __fadd_rn(hcx, 1e-10f));
        float cd = cosf(__fmul_rn(__fsub_rn(pa, pb), 0.5f));
        float gam = __fmul_rn(0.5f, __fmul_rn(cd, cd));

        // ---- inject + mag_squash ----
        float sx = __fadd_rn(hcx, __fmul_rn(gam, ijx));
        float sy = __fadd_rn(hcy, __fmul_rn(gam, ijy));
        float sm = __fsqrt_rn(__fadd_rn(__fadd_rn(__fmul_rn(sx, sx), __fmul_rn(sy, sy)), 1e-8f));
        float ps = atan2f(sy, __fadd_rn(sx, 1e-10f));
        float th = tanhf(sm);
        float sps, cps;
        sincosf(ps, &sps, &cps);
        hx = __fmul_rn(th, cps);
        hy = __fmul_rn(th, sps);

        // ---- readout ----
        float v = __fmul_rn(hx, cn);
        v += __shfl_xor_sync(0xffffffffu, v, 8);
        v += __shfl_xor_sync(0xffffffffu, v, 4);
        v += __shfl_xor_sync(0xffffffffu, v, 2);
        v += __shfl_xor_sync(0xffffffffu, v, 1);
        if (n == 0) yp[(size_t)t * DD] = __fadd_rn(__fmul_rn(xv, dsk), v);

        xv = xv2; dv = dv2; cn = cn2;
        u = u2; ijx = ijx2; ijy = ijy2; pa = pa2; e = e2;
    }
}

extern "C" void kernel_launch(void* const* d_in, const int* in_sizes, int n_in,
                              void* d_out, int out_size)
{
    const float *x = 0, *A_log = 0, *W_dt1 = 0, *W_dt2 = 0, *W_B = 0, *W_C = 0, *Dskip = 0;
    for (int i = 0; i < n_in; ++i) {
        const float* p = (const float*)d_in[i];
        int s = in_sizes[i];
        if (s == BB * LL * DD)      { if (!x) x = p; }
        else if (s == NN)           { if (!A_log) A_log = p; }
        else if (s == DD * RR)      { if (!W_dt1) W_dt1 = p; else W_dt2 = p; }
        else if (s == DD * NN)      { if (!W_B) W_B = p; else W_C = p; }
        else if (s == DD)           { if (!Dskip) Dskip = p; }
    }
    float* y = (float*)d_out;

    float *tmp, *delta, *bt, *ct;
    cudaGetSymbolAddress((void**)&tmp,   g_tmp);
    cudaGetSymbolAddress((void**)&delta, g_delta);
    cudaGetSymbolAddress((void**)&bt,    g_Bt);
    cudaGetSymbolAddress((void**)&ct,    g_Ct);

    const int M = BB * LL;  // 2048
    // tmp, Bt, Ct in one fused pass over x (bit-identical chains)
    proj_fused<<<M / 8, 256>>>(x, W_dt1, W_B, W_C, tmp, bt, ct);
    // delta = softplus(tmp @ W_dt2)
    delta_gemm<<<dim3(4, M / 8), 256>>>(tmp, W_dt2, delta);
    // sequential scan: 1024 single-warp blocks, pa software-pipelined
    scan_k<<<1024, 32>>>(x, A_log, Dskip, y);
}